// round 2
// baseline (speedup 1.0000x reference)
#include <cuda_runtime.h>
#include <cstdint>

// Problem constants (fixed by setup_inputs)
#define B_ 4
#define T_ 1024
#define E_ 512
#define H_ 64
#define DK 8

// Scratch for attention output, laid out as A[B*T][E] rows for the combine GEMM.
__device__ float g_attn[B_ * T_ * E_];

// ---- f32x2 packed math helpers (sm_103a) ----
#define FMA2(d, a, b, c) \
    asm("fma.rn.f32x2 %0, %1, %2, %3;" : "=l"(d) : "l"(a), "l"(b), "l"(c))
#define ADD2(d, a, b) \
    asm("add.rn.f32x2 %0, %1, %2;" : "=l"(d) : "l"(a), "l"(b))
#define PACK2(d, lo, hi) \
    asm("mov.b64 %0, {%1, %2};" : "=l"(d) : "f"(lo), "f"(hi))
#define UNPACK2(lo, hi, v) \
    asm("mov.b64 {%0, %1}, %2;" : "=f"(lo), "=f"(hi) : "l"(v))

__device__ __forceinline__ float ex2_approx(float s) {
    float e;
    asm("ex2.approx.ftz.f32 %0, %1;" : "=f"(e) : "f"(s));
    return e;
}

// ============================================================================
// Kernel 1: fused proj + per-head attention.
// Grid: B*H*4 = 1024 CTAs; blockIdx.x = (bh << 2) | qblock. 256 threads.
// Each CTA: builds proj^T [8][1024] for its (b,h) head in SMEM, then each
// thread computes the full softmax-attention row for one query (streaming,
// no max-trick needed since |score| <= sqrt(8)).
// ============================================================================
__global__ __launch_bounds__(256)
void qattn_kernel(const float* __restrict__ x, const float* __restrict__ theta) {
    __shared__ float sT[DK * T_];   // transposed proj: sT[j*1024 + t]
    __shared__ float cth[DK];

    const int tid = threadIdx.x;
    const int bh  = blockIdx.x >> 2;   // 0..255
    const int qb  = blockIdx.x & 3;
    const int b   = bh >> 6;
    const int h   = bh & 63;

    if (tid < DK) cth[tid] = __cosf(theta[tid]);
    __syncthreads();

    // Build transposed proj tile. Coalesced float4 reads of x, scatter to SMEM.
    const float* xb = x + ((size_t)b * T_) * E_ + h * DK;
    for (int c = tid; c < T_ * 2; c += 256) {
        int t = c >> 1;
        int half = (c & 1) << 2;
        float4 v = *(const float4*)(xb + (size_t)t * E_ + half);
        sT[(half + 0) * T_ + t] = __cosf(v.x) * cth[half + 0];
        sT[(half + 1) * T_ + t] = __cosf(v.y) * cth[half + 1];
        sT[(half + 2) * T_ + t] = __cosf(v.z) * cth[half + 2];
        sT[(half + 3) * T_ + t] = __cosf(v.w) * cth[half + 3];
    }
    __syncthreads();

    const int tq = (qb << 8) + tid;   // this thread's query index

    // Prescale q by (1/sqrt(8)) * log2(e) so scores feed ex2 directly.
    const float SC = 0.35355339059327373f * 1.4426950408889634f;
    unsigned long long qq[DK];
    #pragma unroll
    for (int j = 0; j < DK; j++) {
        float q = sT[j * T_ + tq] * SC;
        PACK2(qq[j], q, q);
    }

    unsigned long long acc01[DK], acc23[DK];
    #pragma unroll
    for (int j = 0; j < DK; j++) { acc01[j] = 0ull; acc23[j] = 0ull; }
    unsigned long long l01 = 0ull, l23 = 0ull;

    // 4 keys per iteration: one LDS.128 per dim j gives {k,k+1,k+2,k+3} packed.
    #pragma unroll 2
    for (int k4 = 0; k4 < T_; k4 += 4) {
        unsigned long long kk01[DK], kk23[DK];
        #pragma unroll
        for (int j = 0; j < DK; j++) {
            ulonglong2 kv = *(const ulonglong2*)&sT[j * T_ + k4];
            kk01[j] = kv.x;
            kk23[j] = kv.y;
        }
        // Scores: two independent depth-4 chains per pair for ILP.
        unsigned long long s01a = 0ull, s01b = 0ull, s23a = 0ull, s23b = 0ull;
        #pragma unroll
        for (int j = 0; j < 4; j++) {
            FMA2(s01a, qq[j], kk01[j], s01a);
            FMA2(s23a, qq[j], kk23[j], s23a);
            FMA2(s01b, qq[j + 4], kk01[j + 4], s01b);
            FMA2(s23b, qq[j + 4], kk23[j + 4], s23b);
        }
        unsigned long long s01, s23;
        ADD2(s01, s01a, s01b);
        ADD2(s23, s23a, s23b);

        float sa, sb, sc, sd;
        UNPACK2(sa, sb, s01);
        UNPACK2(sc, sd, s23);
        float ea = ex2_approx(sa);
        float eb = ex2_approx(sb);
        float ec = ex2_approx(sc);
        float ed = ex2_approx(sd);
        unsigned long long e01, e23;
        PACK2(e01, ea, eb);
        PACK2(e23, ec, ed);
        ADD2(l01, l01, e01);
        ADD2(l23, l23, e23);

        #pragma unroll
        for (int j = 0; j < DK; j++) {
            FMA2(acc01[j], e01, kk01[j], acc01[j]);
            FMA2(acc23[j], e23, kk23[j], acc23[j]);
        }
    }

    float la, lb, lc, ld;
    UNPACK2(la, lb, l01);
    UNPACK2(lc, ld, l23);
    float inv = 1.0f / ((la + lb) + (lc + ld));

    float o[DK];
    #pragma unroll
    for (int j = 0; j < DK; j++) {
        float a0, a1, a2, a3;
        UNPACK2(a0, a1, acc01[j]);
        UNPACK2(a2, a3, acc23[j]);
        o[j] = ((a0 + a1) + (a2 + a3)) * inv;
    }

    float* outp = g_attn + ((size_t)(b * T_ + tq)) * E_ + h * DK;
    *(float4*)(outp + 0) = make_float4(o[0], o[1], o[2], o[3]);
    *(float4*)(outp + 4) = make_float4(o[4], o[5], o[6], o[7]);
}

// ============================================================================
// Kernel 2: combine GEMM. C[m,n] = sum_k A[m,k] * W[n,k] + bias[n]
// A = g_attn [4096 x 512], W [512 x 512] row-major. Classic 64x64 tile,
// 4x4 microtile per thread, 256 threads.
// ============================================================================
__global__ __launch_bounds__(256)
void combine_kernel(const float* __restrict__ W, const float* __restrict__ bias,
                    float* __restrict__ C) {
    __shared__ float As[16][68];
    __shared__ float Ws[16][68];

    const int tid  = threadIdx.x;
    const int row0 = blockIdx.y * 64;
    const int col0 = blockIdx.x * 64;

    const int lm = tid >> 2;          // 0..63 (tile row for loads)
    const int lk = (tid & 3) << 2;    // 0,4,8,12 (k offset for loads)
    const int tm = (tid >> 4) << 2;   // 0..60 micro row
    const int tn = (tid & 15) << 2;   // 0..60 micro col

    const float* Ap = g_attn + (size_t)(row0 + lm) * E_ + lk;
    const float* Wp = W      + (size_t)(col0 + lm) * E_ + lk;

    float acc[4][4] = {};

    for (int k0 = 0; k0 < E_; k0 += 16) {
        float4 av = *(const float4*)(Ap + k0);
        float4 wv = *(const float4*)(Wp + k0);
        As[lk + 0][lm] = av.x; As[lk + 1][lm] = av.y;
        As[lk + 2][lm] = av.z; As[lk + 3][lm] = av.w;
        Ws[lk + 0][lm] = wv.x; Ws[lk + 1][lm] = wv.y;
        Ws[lk + 2][lm] = wv.z; Ws[lk + 3][lm] = wv.w;
        __syncthreads();

        #pragma unroll
        for (int kk = 0; kk < 16; kk++) {
            float4 a4 = *(const float4*)&As[kk][tm];
            float4 w4 = *(const float4*)&Ws[kk][tn];
            float a[4] = {a4.x, a4.y, a4.z, a4.w};
            float w[4] = {w4.x, w4.y, w4.z, w4.w};
            #pragma unroll
            for (int i = 0; i < 4; i++)
                #pragma unroll
                for (int j = 0; j < 4; j++)
                    acc[i][j] += a[i] * w[j];
        }
        __syncthreads();
    }

    float4 bi = *(const float4*)&bias[col0 + tn];
    #pragma unroll
    for (int i = 0; i < 4; i++) {
        float4 ov = make_float4(acc[i][0] + bi.x, acc[i][1] + bi.y,
                                acc[i][2] + bi.z, acc[i][3] + bi.w);
        *(float4*)&C[(size_t)(row0 + tm + i) * E_ + col0 + tn] = ov;
    }
}

extern "C" void kernel_launch(void* const* d_in, const int* in_sizes, int n_in,
                              void* d_out, int out_size) {
    const float* x     = (const float*)d_in[0];
    const float* theta = (const float*)d_in[1];
    const float* W     = (const float*)d_in[2];
    const float* bias  = (const float*)d_in[3];
    float* out = (float*)d_out;

    qattn_kernel<<<B_ * H_ * 4, 256>>>(x, theta);
    dim3 g2(E_ / 64, (B_ * T_) / 64);
    combine_kernel<<<g2, 256>>>(W, bias, out);
}